// round 1
// baseline (speedup 1.0000x reference)
#include <cuda_runtime.h>

#define B_ 2
#define T_ 1024
#define H_ 8
#define D_ 64
#define NLEV_ 11
#define BT 64
#define LD 68          // 64 + 4 pad; 68*4B = 272B rows, 16B-aligned for float4
#define NTHREADS 256
#define NBH (B_*H_)
#define NRT (T_/BT)

// scratch: per-(b,h) inclusive cumsum of gates over T
__device__ float g_cg[NBH * T_];

// ---------------------------------------------------------------------------
// cumsum of g[b,t,h] over t, one block per (b,h)
// ---------------------------------------------------------------------------
__global__ void cumsum_kernel(const float* __restrict__ g) {
    __shared__ float s[T_];
    int bh = blockIdx.x;
    int b = bh >> 3, h = bh & 7;
    int t = threadIdx.x;
    s[t] = g[(b * T_ + t) * H_ + h];
    __syncthreads();
#pragma unroll
    for (int off = 1; off < T_; off <<= 1) {
        float add = (t >= off) ? s[t - off] : 0.0f;
        __syncthreads();
        s[t] += add;
        __syncthreads();
    }
    g_cg[bh * T_ + t] = s[t];
}

// ---------------------------------------------------------------------------
// main kernel: one CTA per (bh, row-tile). Computes
//   O[l,:] = sum_{c<=l} exp(cg[l]-cg[c]) * L[bh, bitlen(l^c), l] * (q_l.k_c) * v_c
// ---------------------------------------------------------------------------
__global__ __launch_bounds__(NTHREADS) void hattn_kernel(
    const float* __restrict__ q, const float* __restrict__ k,
    const float* __restrict__ v, const float* __restrict__ Lsc,
    float* __restrict__ out)
{
    extern __shared__ float sm[];
    float* Qt  = sm;                 // [D_][LD]   Qt[d][l]
    float* KSt = Qt + D_ * LD;       // Kt[d][c] during GEMM1, St[c][l] after
    float* Vs  = KSt + D_ * LD;      // [BT][LD]   Vs[c][p]
    float* Ls  = Vs + BT * LD;       // [NLEV_][BT]
    float* eqs = Ls + NLEV_ * BT;    // [BT] exp(+cg) of rows
    float* eks = eqs + BT;           // [BT] exp(-cg) of cols

    int lin = blockIdx.x;
    int bh  = lin & (NBH - 1);
    int rt  = (NRT - 1) - (lin >> 4);   // heavy row-tiles first
    int b   = bh >> 3, h = bh & 7;
    int tid = threadIdx.x;
    int ty  = tid >> 4, tx = tid & 15;  // 16x16 thread grid, 4x4 per thread
    int row0 = rt * BT;

    // load Q tile (transposed), level-scale rows, row exp-factors
    for (int idx = tid; idx < BT * D_; idx += NTHREADS) {
        int l = idx >> 6, d = idx & 63;
        Qt[d * LD + l] = q[((size_t)((b * T_ + row0 + l) * H_ + h)) * D_ + d];
    }
    for (int idx = tid; idx < NLEV_ * BT; idx += NTHREADS) {
        int lev = idx >> 6, l = idx & 63;
        Ls[lev * BT + l] = Lsc[((size_t)(bh * NLEV_ + lev)) * T_ + row0 + l];
    }
    if (tid < BT) eqs[tid] = expf(g_cg[bh * T_ + row0 + tid]);

    float acc[4][4] = {};

    for (int ct = 0; ct <= rt; ct++) {
        __syncthreads();   // previous iteration's readers of KSt/Vs are done
        int col0 = ct * BT;
        for (int idx = tid; idx < BT * D_; idx += NTHREADS) {
            int c = idx >> 6, d = idx & 63;
            size_t gi = ((size_t)((b * T_ + col0 + c) * H_ + h)) * D_ + d;
            KSt[d * LD + c] = k[gi];   // K transposed
            Vs[c * LD + d]  = v[gi];   // V natural
        }
        if (tid < BT) eks[tid] = expf(-g_cg[bh * T_ + col0 + tid]);
        __syncthreads();

        // ---- GEMM1: s[l][c] = q_l . k_c ----
        float s[4][4] = {};
#pragma unroll 8
        for (int d = 0; d < D_; d++) {
            float4 a  = *(const float4*)&Qt[d * LD + ty * 4];
            float4 bb = *(const float4*)&KSt[d * LD + tx * 4];
            float av[4] = {a.x, a.y, a.z, a.w};
            float bv[4] = {bb.x, bb.y, bb.z, bb.w};
#pragma unroll
            for (int i = 0; i < 4; i++)
#pragma unroll
                for (int j = 0; j < 4; j++)
                    s[i][j] += av[i] * bv[j];
        }

        // ---- apply hierarchical decay weight ----
        if (ct < rt) {
            // whole tile shares one level: 6 + bitlen(rt^ct); weight is rank-1
            int lev = 6 + (32 - __clz(rt ^ ct));
            const float* Lr = Ls + lev * BT;
            float rw[4], cw[4];
#pragma unroll
            for (int i = 0; i < 4; i++) rw[i] = eqs[ty * 4 + i] * Lr[ty * 4 + i];
#pragma unroll
            for (int j = 0; j < 4; j++) cw[j] = eks[tx * 4 + j];
#pragma unroll
            for (int i = 0; i < 4; i++)
#pragma unroll
                for (int j = 0; j < 4; j++)
                    s[i][j] *= rw[i] * cw[j];
        } else {
            // diagonal tile: per-element level + causal mask
#pragma unroll
            for (int i = 0; i < 4; i++) {
                int li = ty * 4 + i;
                float eqv = eqs[li];
#pragma unroll
                for (int j = 0; j < 4; j++) {
                    int ci = tx * 4 + j;
                    if (ci > li) {
                        s[i][j] = 0.0f;
                    } else {
                        int x = li ^ ci;
                        int lev = x ? (32 - __clz(x)) : 0;
                        s[i][j] *= eqv * eks[ci] * Ls[lev * BT + li];
                    }
                }
            }
        }

        __syncthreads();   // GEMM1 reads of KSt finished
        // store S transposed into the K buffer: St[c][l]
#pragma unroll
        for (int j = 0; j < 4; j++)
#pragma unroll
            for (int i = 0; i < 4; i++)
                KSt[(tx * 4 + j) * LD + ty * 4 + i] = s[i][j];
        __syncthreads();

        // ---- GEMM2: acc[l][p] += sum_c S[l][c] * V[c][p] ----
#pragma unroll 8
        for (int c = 0; c < BT; c++) {
            float4 a  = *(const float4*)&KSt[c * LD + ty * 4];
            float4 bb = *(const float4*)&Vs[c * LD + tx * 4];
            float av[4] = {a.x, a.y, a.z, a.w};
            float bv[4] = {bb.x, bb.y, bb.z, bb.w};
#pragma unroll
            for (int i = 0; i < 4; i++)
#pragma unroll
                for (int j = 0; j < 4; j++)
                    acc[i][j] += av[i] * bv[j];
        }
    }

    // write out[b, l, h, p]
#pragma unroll
    for (int i = 0; i < 4; i++) {
        int l = row0 + ty * 4 + i;
        float4 o = make_float4(acc[i][0], acc[i][1], acc[i][2], acc[i][3]);
        *(float4*)&out[((size_t)((b * T_ + l) * H_ + h)) * D_ + tx * 4] = o;
    }
}

extern "C" void kernel_launch(void* const* d_in, const int* in_sizes, int n_in,
                              void* d_out, int out_size) {
    const float* q   = (const float*)d_in[0];
    const float* k   = (const float*)d_in[1];
    const float* v   = (const float*)d_in[2];
    const float* g   = (const float*)d_in[3];
    const float* Lsc = (const float*)d_in[4];
    float* out = (float*)d_out;

    cumsum_kernel<<<NBH, T_>>>(g);

    int smem = (D_ * LD * 2 + BT * LD + NLEV_ * BT + 2 * BT) * (int)sizeof(float);
    cudaFuncSetAttribute(hattn_kernel, cudaFuncAttributeMaxDynamicSharedMemorySize, smem);
    hattn_kernel<<<NBH * NRT, NTHREADS, smem>>>(q, k, v, Lsc, out);
}

// round 2
// speedup vs baseline: 1.3940x; 1.3940x over previous
#include <cuda_runtime.h>

#define B_ 2
#define T_ 1024
#define H_ 8
#define D_ 64
#define NLEV_ 11
#define BT 64
#define LD 68          // 64 + 4 pad; rows 16B-aligned for float4
#define NTHREADS 256
#define NBH (B_*H_)
#define NRT (T_/BT)
#define CHUNK 4
#define UNITS_PER_BH 40   // sum over rt of ceil((rt+1)/4)

// scratch: per-(b,h) inclusive cumsum of gates; split-K partial outputs
__device__ float g_cg[NBH * T_];
__device__ float g_part[NBH * UNITS_PER_BH * BT * D_];   // ~10.5 MB

// ---------------------------------------------------------------------------
// cumsum of g[b,t,h] over t, one block per (b,h)
// ---------------------------------------------------------------------------
__global__ void cumsum_kernel(const float* __restrict__ g) {
    __shared__ float s[T_];
    int bh = blockIdx.x;
    int b = bh >> 3, h = bh & 7;
    int t = threadIdx.x;
    s[t] = g[(b * T_ + t) * H_ + h];
    __syncthreads();
#pragma unroll
    for (int off = 1; off < T_; off <<= 1) {
        float add = (t >= off) ? s[t - off] : 0.0f;
        __syncthreads();
        s[t] += add;
        __syncthreads();
    }
    g_cg[bh * T_ + t] = s[t];
}

// ---------------------------------------------------------------------------
// main kernel: one CTA per (bh, rt, ct-chunk). Chains of <=4 tile iterations.
// Units enumerated with rt descending; within rt, chunk index ci ascending.
// ---------------------------------------------------------------------------
__global__ __launch_bounds__(NTHREADS) void hattn_kernel(
    const float* __restrict__ q, const float* __restrict__ k,
    const float* __restrict__ v, const float* __restrict__ Lsc)
{
    extern __shared__ float sm[];
    float* Qt  = sm;                 // [D_][LD]   Qt[d][l]
    float* Kt  = Qt + D_ * LD;       // [D_][LD]   Kt[d][c]
    float* Vs  = Kt + D_ * LD;       // [BT][LD]   Vs[c][p]
    float* Ss  = Vs + BT * LD;       // [BT][LD]   St[c][l]  (S transposed)
    float* Ls  = Ss + BT * LD;       // [NLEV_][BT]
    float* eqs = Ls + NLEV_ * BT;    // [BT] exp(+cg) rows
    float* eks = eqs + BT;           // [BT] exp(-cg) cols

    int bh = blockIdx.x & (NBH - 1);
    int u  = blockIdx.x >> 4;
    int rt = NRT - 1;
    while (u >= ((rt >> 2) + 1)) { u -= (rt >> 2) + 1; rt--; }
    int ci = u;                        // chunk index within this rt
    int b  = bh >> 3, h = bh & 7;
    int tid = threadIdx.x;
    int ty  = tid >> 4, tx = tid & 15; // 16x16 threads, 4x4 regs each
    int row0 = rt * BT;

    // unit index (same descending enumeration) for the partial-output slot
    int ubase = 0;
    for (int r = NRT - 1; r > rt; r--) ubase += (r >> 2) + 1;
    int slot = bh * UNITS_PER_BH + ubase + ci;

    // load Q tile (transposed), level-scale rows, row exp-factors
    for (int idx = tid; idx < BT * D_; idx += NTHREADS) {
        int l = idx >> 6, d = idx & 63;
        Qt[d * LD + l] = q[((size_t)((b * T_ + row0 + l) * H_ + h)) * D_ + d];
    }
    for (int idx = tid; idx < NLEV_ * BT; idx += NTHREADS) {
        int lev = idx >> 6, l = idx & 63;
        Ls[lev * BT + l] = Lsc[((size_t)(bh * NLEV_ + lev)) * T_ + row0 + l];
    }
    if (tid < BT) eqs[tid] = expf(g_cg[bh * T_ + row0 + tid]);

    float acc[4][4] = {};
    int ct0 = ci * CHUNK;
    int ct1 = ct0 + CHUNK - 1; if (ct1 > rt) ct1 = rt;

    for (int ct = ct0; ct <= ct1; ct++) {
        __syncthreads();   // prev iter's readers of Kt/Vs/Ss done; Q load done
        int col0 = ct * BT;
        for (int idx = tid; idx < BT * D_; idx += NTHREADS) {
            int c = idx >> 6, d = idx & 63;
            size_t gi = ((size_t)((b * T_ + col0 + c) * H_ + h)) * D_ + d;
            Kt[d * LD + c] = k[gi];    // K transposed
            Vs[c * LD + d] = v[gi];    // V natural
        }
        if (tid < BT) eks[tid] = expf(-g_cg[bh * T_ + col0 + tid]);
        __syncthreads();

        // ---- GEMM1: s[l][c] = q_l . k_c ----
        float s[4][4] = {};
#pragma unroll 8
        for (int d = 0; d < D_; d++) {
            float4 a  = *(const float4*)&Qt[d * LD + ty * 4];
            float4 bb = *(const float4*)&Kt[d * LD + tx * 4];
            float av[4] = {a.x, a.y, a.z, a.w};
            float bv[4] = {bb.x, bb.y, bb.z, bb.w};
#pragma unroll
            for (int i = 0; i < 4; i++)
#pragma unroll
                for (int j = 0; j < 4; j++)
                    s[i][j] += av[i] * bv[j];
        }

        // ---- hierarchical decay weight ----
        if (ct < rt) {
            // off-diagonal tile: constant level, rank-1 weight
            int lev = 6 + (32 - __clz(rt ^ ct));
            const float* Lr = Ls + lev * BT;
            float rw[4], cw[4];
#pragma unroll
            for (int i = 0; i < 4; i++) rw[i] = eqs[ty * 4 + i] * Lr[ty * 4 + i];
#pragma unroll
            for (int j = 0; j < 4; j++) cw[j] = eks[tx * 4 + j];
#pragma unroll
            for (int i = 0; i < 4; i++)
#pragma unroll
                for (int j = 0; j < 4; j++)
                    s[i][j] *= rw[i] * cw[j];
        } else {
            // diagonal tile: per-element level + causal mask
#pragma unroll
            for (int i = 0; i < 4; i++) {
                int li = ty * 4 + i;
                float eqv = eqs[li];
#pragma unroll
                for (int j = 0; j < 4; j++) {
                    int cj = tx * 4 + j;
                    if (cj > li) {
                        s[i][j] = 0.0f;
                    } else {
                        int x = li ^ cj;
                        int lev = x ? (32 - __clz(x)) : 0;
                        s[i][j] *= eqv * eks[cj] * Ls[lev * BT + li];
                    }
                }
            }
        }

        // store S transposed into its own buffer (no extra barrier needed
        // before the store: Ss readers finished at the loop-top sync)
#pragma unroll
        for (int j = 0; j < 4; j++)
#pragma unroll
            for (int i = 0; i < 4; i++)
                Ss[(tx * 4 + j) * LD + ty * 4 + i] = s[i][j];
        __syncthreads();

        // ---- GEMM2: acc[l][p] += sum_c S[l][c] * V[c][p] ----
#pragma unroll 8
        for (int c = 0; c < BT; c++) {
            float4 a  = *(const float4*)&Ss[c * LD + ty * 4];
            float4 bb = *(const float4*)&Vs[c * LD + tx * 4];
            float av[4] = {a.x, a.y, a.z, a.w};
            float bv[4] = {bb.x, bb.y, bb.z, bb.w};
#pragma unroll
            for (int i = 0; i < 4; i++)
#pragma unroll
                for (int j = 0; j < 4; j++)
                    acc[i][j] += av[i] * bv[j];
        }
    }

    // write partial tile [64][64] for this unit
    float* pbase = g_part + (size_t)slot * BT * D_;
#pragma unroll
    for (int i = 0; i < 4; i++) {
        float4 o = make_float4(acc[i][0], acc[i][1], acc[i][2], acc[i][3]);
        *(float4*)&pbase[(ty * 4 + i) * D_ + tx * 4] = o;
    }
}

// ---------------------------------------------------------------------------
// deterministic reduction: out[b,l,h,p] = sum_ci partial[bh][ubase(rt)+ci][li][p]
// ---------------------------------------------------------------------------
__global__ void reduce_kernel(float* __restrict__ out) {
    int f4 = blockIdx.x * blockDim.x + threadIdx.x;     // float4 index
    int e  = f4 * 4;
    int p  = e & 63;
    int h  = (e >> 6) & 7;
    int l  = (e >> 9) & (T_ - 1);
    int b  = e >> 19;
    int bh = b * H_ + h;
    int rt = l >> 6, li = l & 63;
    int nch = (rt >> 2) + 1;
    int ubase = 0;
    for (int r = NRT - 1; r > rt; r--) ubase += (r >> 2) + 1;
    const float* pb = g_part + ((size_t)(bh * UNITS_PER_BH + ubase) * BT + li) * D_ + p;
    float4 s = make_float4(0.f, 0.f, 0.f, 0.f);
    for (int c = 0; c < nch; c++) {
        float4 t = *(const float4*)(pb + (size_t)c * BT * D_);
        s.x += t.x; s.y += t.y; s.z += t.z; s.w += t.w;
    }
    *(float4*)&out[e] = s;
}

extern "C" void kernel_launch(void* const* d_in, const int* in_sizes, int n_in,
                              void* d_out, int out_size) {
    const float* q   = (const float*)d_in[0];
    const float* k   = (const float*)d_in[1];
    const float* v   = (const float*)d_in[2];
    const float* g   = (const float*)d_in[3];
    const float* Lsc = (const float*)d_in[4];
    float* out = (float*)d_out;

    cumsum_kernel<<<NBH, T_>>>(g);

    int smem = (D_ * LD * 2 + BT * LD * 2 + NLEV_ * BT + 2 * BT) * (int)sizeof(float);
    cudaFuncSetAttribute(hattn_kernel, cudaFuncAttributeMaxDynamicSharedMemorySize, smem);
    hattn_kernel<<<NBH * UNITS_PER_BH, NTHREADS, smem>>>(q, k, v, Lsc);

    int nf4 = B_ * T_ * H_ * D_ / 4;
    reduce_kernel<<<nf4 / 256, 256>>>(out);
}

// round 13
// speedup vs baseline: 2.5699x; 1.8435x over previous
#include <cuda_runtime.h>

#define B_ 2
#define T_ 1024
#define H_ 8
#define D_ 64
#define NLEV_ 11
#define BT 64
#define SLD 72               // bf16 elems per smem row (64 + 8 pad) -> 144B rows
#define NTHREADS 256
#define NBH (B_*H_)
#define NRT (T_/BT)
#define CHUNK 4
#define UPB 40               // sum over rt of ceil((rt+1)/4)

// smem byte offsets
#define O_QH 0
#define O_QL 9216
#define O_KH 18432
#define O_KL 27648
#define O_VH 36864
#define O_VL 46080
#define O_SH 55296
#define O_SL 64512
#define O_LS 73728           // 11*64 floats
#define O_EQ 76544           // 64 floats
#define O_EK 76800           // 64 floats
#define SMEM_TOTAL 77056

__device__ float g_cg[NBH * T_];
__device__ float g_part[NBH * UPB * BT * D_];   // 10.5 MB

__device__ __forceinline__ unsigned su32(const void* p) {
    unsigned a;
    asm("{ .reg .u64 t; cvta.to.shared.u64 t, %1; cvt.u32.u64 %0, t; }" : "=r"(a) : "l"(p));
    return a;
}
#define LDSM4(r0,r1,r2,r3,a) \
    asm volatile("ldmatrix.sync.aligned.m8n8.x4.shared.b16 {%0,%1,%2,%3}, [%4];" \
                 : "=r"(r0),"=r"(r1),"=r"(r2),"=r"(r3) : "r"(a))
#define LDSM4T(r0,r1,r2,r3,a) \
    asm volatile("ldmatrix.sync.aligned.m8n8.x4.trans.shared.b16 {%0,%1,%2,%3}, [%4];" \
                 : "=r"(r0),"=r"(r1),"=r"(r2),"=r"(r3) : "r"(a))
#define MMA16816(d,a0,a1,a2,a3,b0,b1) \
    asm volatile("mma.sync.aligned.m16n8k16.row.col.f32.bf16.bf16.f32 " \
                 "{%0,%1,%2,%3},{%4,%5,%6,%7},{%8,%9},{%0,%1,%2,%3};" \
                 : "+f"((d)[0]),"+f"((d)[1]),"+f"((d)[2]),"+f"((d)[3]) \
                 : "r"(a0),"r"(a1),"r"(a2),"r"(a3),"r"(b0),"r"(b1))

__device__ __forceinline__ unsigned pack_lo2(float x, float y) {
    unsigned r;
    asm("cvt.rn.bf16x2.f32 %0, %1, %2;" : "=r"(r) : "f"(y), "f"(x));  // y->hi, x->lo
    return r;
}

// ---------------------------------------------------------------------------
__global__ void cumsum_kernel(const float* __restrict__ g) {
    __shared__ float ws[32];
    int bh = blockIdx.x, b = bh >> 3, h = bh & 7;
    int t = threadIdx.x, lane = t & 31, wid = t >> 5;
    float v = g[(b * T_ + t) * H_ + h];
#pragma unroll
    for (int o = 1; o < 32; o <<= 1) {
        float n = __shfl_up_sync(0xFFFFFFFFu, v, o);
        if (lane >= o) v += n;
    }
    if (lane == 31) ws[wid] = v;
    __syncthreads();
    if (wid == 0) {
        float s = ws[lane];
#pragma unroll
        for (int o = 1; o < 32; o <<= 1) {
            float n = __shfl_up_sync(0xFFFFFFFFu, s, o);
            if (lane >= o) s += n;
        }
        ws[lane] = s;
    }
    __syncthreads();
    if (wid > 0) v += ws[wid - 1];
    g_cg[bh * T_ + t] = v;
}

// split one float4 to bf16 hi/lo pairs and store at offset
__device__ __forceinline__ void split_store(float4 f, char* hi, char* lo, unsigned off) {
    unsigned bx = __float_as_uint(f.x) & 0xFFFF0000u;
    unsigned by = __float_as_uint(f.y) & 0xFFFF0000u;
    unsigned bz = __float_as_uint(f.z) & 0xFFFF0000u;
    unsigned bw = __float_as_uint(f.w) & 0xFFFF0000u;
    unsigned h01 = (bx >> 16) | by, h23 = (bz >> 16) | bw;
    unsigned l01 = pack_lo2(f.x - __uint_as_float(bx), f.y - __uint_as_float(by));
    unsigned l23 = pack_lo2(f.z - __uint_as_float(bz), f.w - __uint_as_float(bw));
    *(uint2*)(hi + off) = make_uint2(h01, h23);
    *(uint2*)(lo + off) = make_uint2(l01, l23);
}

// ---------------------------------------------------------------------------
__global__ __launch_bounds__(NTHREADS) void hattn_kernel(
    const float* __restrict__ q, const float* __restrict__ k,
    const float* __restrict__ v, const float* __restrict__ Lsc)
{
    extern __shared__ char sm[];
    unsigned su = su32(sm);
    float* eqs = (float*)(sm + O_EQ);
    float* eks = (float*)(sm + O_EK);
    float* Lss = (float*)(sm + O_LS);

    int bh = blockIdx.x & (NBH - 1);
    int u  = blockIdx.x >> 4;
    int rt = NRT - 1;
    while (u >= ((rt >> 2) + 1)) { u -= (rt >> 2) + 1; rt--; }
    int ci = u;
    int ubase = 0;
    for (int r = NRT - 1; r > rt; r--) ubase += (r >> 2) + 1;
    int slot = bh * UPB + ubase + ci;
    int ct0 = ci * CHUNK;
    int ct1 = ct0 + CHUNK - 1; if (ct1 > rt) ct1 = rt;

    int b = bh >> 3, h = bh & 7;
    int tid = threadIdx.x, lane = tid & 31, w = tid >> 5;
    int wm = w & 3, wn = w >> 2;           // warp tile: rows wm*16, cols wn*32
    int m0 = wm * 16, n0 = wn * 32;
    int row0 = rt * BT;

    // per-thread gather pattern for 64x64 tile loads (4 float4 each)
    int pr[4], pc[4];
#pragma unroll
    for (int it = 0; it < 4; it++) {
        int idx = tid + it * NTHREADS;
        pr[it] = idx >> 4;
        pc[it] = (idx & 15) << 2;
    }

    // load + split Q tile
    {
        const float* qs = q + ((size_t)(b * T_ + row0) * H_ + h) * D_;
#pragma unroll
        for (int it = 0; it < 4; it++) {
            float4 f = *(const float4*)(qs + (size_t)pr[it] * (H_ * D_) + pc[it]);
            split_store(f, sm + O_QH, sm + O_QL, (unsigned)(pr[it] * SLD + pc[it]) * 2);
        }
    }
    for (int idx = tid; idx < NLEV_ * BT; idx += NTHREADS) {
        int lev = idx >> 6, l = idx & 63;
        Lss[idx] = Lsc[((size_t)(bh * NLEV_ + lev)) * T_ + row0 + l];
    }
    if (tid < BT) eqs[tid] = expf(g_cg[bh * T_ + row0 + tid]);

    float o[16] = {};                       // O accum: 4 n8-tiles x 4
    int r0 = m0 + (lane >> 2);
    int cq = (lane & 3) * 2;

    // lane-constant address pieces
    unsigned a_row = (unsigned)(m0 + (lane & 15)) * SLD;   // A frag rows
    unsigned a_k8  = ((lane >> 4) << 3);                   // A k-half per 16 lanes
    unsigned b_row = (unsigned)(((lane >> 4) << 3) + (lane & 7));  // GEMM1 B: n rows
    unsigned b_k8  = (((lane >> 3) & 1) << 3);                     // GEMM1 B: k-half
    unsigned v_row = (unsigned)((lane & 7) + (((lane >> 3) & 1) << 3)); // GEMM2 V: k row
    unsigned v_col = ((lane >> 4) << 3);                                // GEMM2 V: n-half

    // prefetch first K/V tile into registers
    float4 kf[4], vf[4];
    {
        const float* ks = k + ((size_t)(b * T_ + ct0 * BT) * H_ + h) * D_;
        const float* vs = v + ((size_t)(b * T_ + ct0 * BT) * H_ + h) * D_;
#pragma unroll
        for (int it = 0; it < 4; it++) {
            kf[it] = *(const float4*)(ks + (size_t)pr[it] * (H_ * D_) + pc[it]);
            vf[it] = *(const float4*)(vs + (size_t)pr[it] * (H_ * D_) + pc[it]);
        }
    }

    for (int ct = ct0; ct <= ct1; ct++) {
        __syncthreads();                    // prev GEMM2 finished reading smem
#pragma unroll
        for (int it = 0; it < 4; it++) {
            unsigned off = (unsigned)(pr[it] * SLD + pc[it]) * 2;
            split_store(kf[it], sm + O_KH, sm + O_KL, off);
            split_store(vf[it], sm + O_VH, sm + O_VL, off);
        }
        if (tid < BT) eks[tid] = expf(-g_cg[bh * T_ + ct * BT + tid]);
        __syncthreads();

        // ---- GEMM1: S = Qh*Kh + Qh*Kl + Ql*Kh ----
        float sa[16] = {};
#pragma unroll
        for (int p = 0; p < 3; p++) {
            unsigned ab = su + (p == 2 ? O_QL : O_QH);
            unsigned bb = su + (p == 1 ? O_KL : O_KH);
#pragma unroll
            for (int kk = 0; kk < 4; kk++) {
                unsigned k0 = kk * 16;
                unsigned a0, a1, a2, a3;
                LDSM4(a0, a1, a2, a3, ab + (a_row + k0 + a_k8) * 2);
#pragma unroll
                for (int nn = 0; nn < 2; nn++) {
                    unsigned b0, b1, b2, b3;
                    unsigned ba = bb + (((unsigned)(n0 + nn * 16) + b_row) * SLD + k0 + b_k8) * 2;
                    LDSM4(b0, b1, b2, b3, ba);
                    MMA16816(sa + (nn * 2 + 0) * 4, a0, a1, a2, a3, b0, b1);
                    MMA16816(sa + (nn * 2 + 1) * 4, a0, a1, a2, a3, b2, b3);
                }
            }
        }

        // ---- epilogue: hierarchical weight, split, store to S tiles ----
        bool diag = (ct == rt);
        float eq0 = eqs[r0], eq1 = eqs[r0 + 8];
        float rw0 = 0.f, rw1 = 0.f;
        if (!diag) {
            int lev = 6 + (32 - __clz(rt ^ ct));
            rw0 = eq0 * Lss[lev * 64 + r0];
            rw1 = eq1 * Lss[lev * 64 + r0 + 8];
        }
#pragma unroll
        for (int j = 0; j < 4; j++) {
            int c0 = n0 + j * 8 + cq;
            float ek0 = eks[c0], ek1 = eks[c0 + 1];
            float s00 = sa[j * 4 + 0], s01 = sa[j * 4 + 1];
            float s10 = sa[j * 4 + 2], s11 = sa[j * 4 + 3];
            if (!diag) {
                s00 *= rw0 * ek0; s01 *= rw0 * ek1;
                s10 *= rw1 * ek0; s11 *= rw1 * ek1;
            } else {
                int x;
                x = r0 ^ c0;
                s00 = (c0 > r0) ? 0.f : s00 * eq0 * ek0 * Lss[(x ? 32 - __clz(x) : 0) * 64 + r0];
                x = r0 ^ (c0 + 1);
                s01 = (c0 + 1 > r0) ? 0.f : s01 * eq0 * ek1 * Lss[(x ? 32 - __clz(x) : 0) * 64 + r0];
                x = (r0 + 8) ^ c0;
                s10 = (c0 > r0 + 8) ? 0.f : s10 * eq1 * ek0 * Lss[(x ? 32 - __clz(x) : 0) * 64 + r0 + 8];
                x = (r0 + 8) ^ (c0 + 1);
                s11 = (c0 + 1 > r0 + 8) ? 0.f : s11 * eq1 * ek1 * Lss[(x ? 32 - __clz(x) : 0) * 64 + r0 + 8];
            }
            unsigned h0 = ((__float_as_uint(s00) & 0xFFFF0000u) >> 16) | (__float_as_uint(s01) & 0xFFFF0000u);
            unsigned h1 = ((__float_as_uint(s10) & 0xFFFF0000u) >> 16) | (__float_as_uint(s11) & 0xFFFF0000u);
            float t00 = s00 - __uint_as_float(__float_as_uint(s00) & 0xFFFF0000u);
            float t01 = s01 - __uint_as_float(__float_as_uint(s01) & 0xFFFF0000u);
            float t10 = s10 - __uint_as_float(__float_as_uint(s10) & 0xFFFF0000u);
            float t11 = s11 - __uint_as_float(__float_as_uint(s11) & 0xFFFF0000u);
            unsigned off0 = (unsigned)(r0 * SLD + c0) * 2;
            unsigned off1 = (unsigned)((r0 + 8) * SLD + c0) * 2;
            *(unsigned*)(sm + O_SH + off0) = h0;
            *(unsigned*)(sm + O_SH + off1) = h1;
            *(unsigned*)(sm + O_SL + off0) = pack_lo2(t00, t01);
            *(unsigned*)(sm + O_SL + off1) = pack_lo2(t10, t11);
        }

        // prefetch next tile's K/V (overlaps with GEMM2 below)
        if (ct < ct1) {
            const float* ks = k + ((size_t)(b * T_ + (ct + 1) * BT) * H_ + h) * D_;
            const float* vs = v + ((size_t)(b * T_ + (ct + 1) * BT) * H_ + h) * D_;
#pragma unroll
            for (int it = 0; it < 4; it++) {
                kf[it] = *(const float4*)(ks + (size_t)pr[it] * (H_ * D_) + pc[it]);
                vf[it] = *(const float4*)(vs + (size_t)pr[it] * (H_ * D_) + pc[it]);
            }
        }
        __syncthreads();

        // ---- GEMM2: O += Sh*Vh + Sh*Vl + Sl*Vh  (V via ldmatrix.trans) ----
#pragma unroll
        for (int p = 0; p < 3; p++) {
            unsigned ab = su + (p == 2 ? O_SL : O_SH);
            unsigned bb = su + (p == 1 ? O_VL : O_VH);
#pragma unroll
            for (int kk = 0; kk < 4; kk++) {
                unsigned k0 = kk * 16;
                unsigned a0, a1, a2, a3;
                LDSM4(a0, a1, a2, a3, ab + (a_row + k0 + a_k8) * 2);
#pragma unroll
                for (int nn = 0; nn < 2; nn++) {
                    unsigned b0, b1, b2, b3;
                    unsigned va = bb + ((k0 + v_row) * SLD + (unsigned)(n0 + nn * 16) + v_col) * 2;
                    LDSM4T(b0, b1, b2, b3, va);
                    MMA16816(o + (nn * 2 + 0) * 4, a0, a1, a2, a3, b0, b1);
                    MMA16816(o + (nn * 2 + 1) * 4, a0, a1, a2, a3, b2, b3);
                }
            }
        }
    }

    // ---- write split-K partial [64 x 64] ----
    float* pb = g_part + (size_t)slot * BT * D_;
#pragma unroll
    for (int j = 0; j < 4; j++) {
        int c0 = n0 + j * 8 + cq;
        *(float2*)(pb + r0 * D_ + c0)       = make_float2(o[j * 4 + 0], o[j * 4 + 1]);
        *(float2*)(pb + (r0 + 8) * D_ + c0) = make_float2(o[j * 4 + 2], o[j * 4 + 3]);
    }
}

// ---------------------------------------------------------------------------
__global__ void reduce_kernel(float* __restrict__ out) {
    int e = (blockIdx.x * blockDim.x + threadIdx.x) * 4;
    int p = e & 63, h = (e >> 6) & 7, l = (e >> 9) & (T_ - 1), b = e >> 19;
    int bh = b * H_ + h;
    int rt = l >> 6, li = l & 63;
    int nch = (rt >> 2) + 1;
    int ubase = 0;
    for (int r = NRT - 1; r > rt; r--) ubase += (r >> 2) + 1;
    const float* pb = g_part + ((size_t)(bh * UPB + ubase) * BT + li) * D_ + p;
    float4 s = make_float4(0.f, 0.f, 0.f, 0.f);
    for (int c = 0; c < nch; c++) {
        float4 t = *(const float4*)(pb + (size_t)c * BT * D_);
        s.x += t.x; s.y += t.y; s.z += t.z; s.w += t.w;
    }
    *(float4*)&out[e] = s;
}

extern "C" void kernel_launch(void* const* d_in, const int* in_sizes, int n_in,
                              void* d_out, int out_size) {
    const float* q   = (const float*)d_in[0];
    const float* k   = (const float*)d_in[1];
    const float* v   = (const float*)d_in[2];
    const float* g   = (const float*)d_in[3];
    const float* Lsc = (const float*)d_in[4];
    float* out = (float*)d_out;

    cumsum_kernel<<<NBH, T_>>>(g);

    cudaFuncSetAttribute(hattn_kernel, cudaFuncAttributeMaxDynamicSharedMemorySize, SMEM_TOTAL);
    hattn_kernel<<<NBH * UPB, NTHREADS, SMEM_TOTAL>>>(q, k, v, Lsc);

    int nf4 = B_ * T_ * H_ * D_ / 4;
    reduce_kernel<<<nf4 / 256, 256>>>(out);
}

// round 14
// speedup vs baseline: 3.2922x; 1.2811x over previous
#include <cuda_runtime.h>

#define B_ 2
#define T_ 1024
#define H_ 8
#define D_ 64
#define NLEV_ 11
#define BT 64
#define SLD 72               // bf16 elems per smem row (64 + 8 pad) -> 144B rows
#define NTHREADS 256
#define NBH (B_*H_)
#define NRT (T_/BT)
#define CHUNK 4
#define UPB 40               // sum over rt of ceil((rt+1)/4)

// smem byte offsets
#define O_QH 0
#define O_QL 9216
#define O_KH 18432
#define O_KL 27648
#define O_VH 36864
#define O_VL 46080
#define O_SH 55296
#define O_SL 64512
#define O_LS 73728           // 11*64 floats
#define O_EQ 76544           // 64 floats
#define O_EK 76800           // 64 floats
#define O_SCR 77056          // 1024 floats: CTA-local gate prefix sums
#define SMEM_TOTAL 81152

__device__ float g_part[NBH * NRT * 4 * BT * D_];   // split-K partials (16.8 MB)
__device__ int   g_cnt[NBH * NRT];                  // arrival counters (zero-init)

__device__ __forceinline__ unsigned su32(const void* p) {
    unsigned a;
    asm("{ .reg .u64 t; cvta.to.shared.u64 t, %1; cvt.u32.u64 %0, t; }" : "=r"(a) : "l"(p));
    return a;
}
#define LDSM4(r0,r1,r2,r3,a) \
    asm volatile("ldmatrix.sync.aligned.m8n8.x4.shared.b16 {%0,%1,%2,%3}, [%4];" \
                 : "=r"(r0),"=r"(r1),"=r"(r2),"=r"(r3) : "r"(a))
#define LDSM4T(r0,r1,r2,r3,a) \
    asm volatile("ldmatrix.sync.aligned.m8n8.x4.trans.shared.b16 {%0,%1,%2,%3}, [%4];" \
                 : "=r"(r0),"=r"(r1),"=r"(r2),"=r"(r3) : "r"(a))
#define MMA16816(d,a0,a1,a2,a3,b0,b1) \
    asm volatile("mma.sync.aligned.m16n8k16.row.col.f32.bf16.bf16.f32 " \
                 "{%0,%1,%2,%3},{%4,%5,%6,%7},{%8,%9},{%0,%1,%2,%3};" \
                 : "+f"((d)[0]),"+f"((d)[1]),"+f"((d)[2]),"+f"((d)[3]) \
                 : "r"(a0),"r"(a1),"r"(a2),"r"(a3),"r"(b0),"r"(b1))

__device__ __forceinline__ unsigned pack_lo2(float x, float y) {
    unsigned r;
    asm("cvt.rn.bf16x2.f32 %0, %1, %2;" : "=r"(r) : "f"(y), "f"(x));  // y->hi, x->lo
    return r;
}

// split one float4 to bf16 hi/lo pairs and store at offset
__device__ __forceinline__ void split_store(float4 f, char* hi, char* lo, unsigned off) {
    unsigned bx = __float_as_uint(f.x) & 0xFFFF0000u;
    unsigned by = __float_as_uint(f.y) & 0xFFFF0000u;
    unsigned bz = __float_as_uint(f.z) & 0xFFFF0000u;
    unsigned bw = __float_as_uint(f.w) & 0xFFFF0000u;
    unsigned h01 = (bx >> 16) | by, h23 = (bz >> 16) | bw;
    unsigned l01 = pack_lo2(f.x - __uint_as_float(bx), f.y - __uint_as_float(by));
    unsigned l23 = pack_lo2(f.z - __uint_as_float(bz), f.w - __uint_as_float(bw));
    *(uint2*)(hi + off) = make_uint2(h01, h23);
    *(uint2*)(lo + off) = make_uint2(l01, l23);
}

// ---------------------------------------------------------------------------
__global__ __launch_bounds__(NTHREADS, 2) void hattn_kernel(
    const float* __restrict__ q, const float* __restrict__ k,
    const float* __restrict__ v, const float* __restrict__ gates,
    const float* __restrict__ Lsc, float* __restrict__ out)
{
    extern __shared__ char sm[];
    __shared__ int lastFlag;
    unsigned su = su32(sm);
    float* eqs = (float*)(sm + O_EQ);
    float* eks = (float*)(sm + O_EK);
    float* Lss = (float*)(sm + O_LS);
    float* scr = (float*)(sm + O_SCR);

    int bh = blockIdx.x & (NBH - 1);
    int u  = blockIdx.x >> 4;
    int rt = NRT - 1;
    while (u >= ((rt >> 2) + 1)) { u -= (rt >> 2) + 1; rt--; }
    int ci = u;
    int ct0 = ci * CHUNK;
    int ct1 = ct0 + CHUNK - 1; if (ct1 > rt) ct1 = rt;
    int nch = (rt >> 2) + 1;

    int b = bh >> 3, h = bh & 7;
    int tid = threadIdx.x, lane = tid & 31, w = tid >> 5;
    int wm = w & 3, wn = w >> 2;           // warp tile: rows wm*16, cols wn*32
    int m0 = wm * 16, n0 = wn * 32;
    int row0 = rt * BT;
    int lo = ct0 * BT;
    int nsc = row0 + BT - lo;              // scan length (<=1024)

    // per-thread gather pattern for 64x64 tile loads (4 float4 each)
    int pr[4], pc[4];
#pragma unroll
    for (int it = 0; it < 4; it++) {
        int idx = tid + it * NTHREADS;
        pr[it] = idx >> 4;
        pc[it] = (idx & 15) << 2;
    }

    // load + split Q tile
    {
        const float* qs = q + ((size_t)(b * T_ + row0) * H_ + h) * D_;
#pragma unroll
        for (int it = 0; it < 4; it++) {
            float4 f = *(const float4*)(qs + (size_t)pr[it] * (H_ * D_) + pc[it]);
            split_store(f, sm + O_QH, sm + O_QL, (unsigned)(pr[it] * SLD + pc[it]) * 2);
        }
    }
    for (int idx = tid; idx < NLEV_ * BT; idx += NTHREADS) {
        int lev = idx >> 6, l = idx & 63;
        Lss[idx] = Lsc[((size_t)(bh * NLEV_ + lev)) * T_ + row0 + l];
    }

    // ---- CTA-local inclusive prefix scan of gates over [lo, row0+64) ----
    {
        float gv[4];
        int bse = tid * 4;
        const float* gp = gates + ((size_t)(b * T_ + lo)) * H_ + h;
#pragma unroll
        for (int j = 0; j < 4; j++) {
            int ix = bse + j;
            gv[j] = (ix < nsc) ? gp[(size_t)ix * H_] : 0.0f;
        }
        float ts = gv[0] + gv[1] + gv[2] + gv[3];
        float sc = ts;
#pragma unroll
        for (int o2 = 1; o2 < 32; o2 <<= 1) {
            float nb = __shfl_up_sync(0xFFFFFFFFu, sc, o2);
            if (lane >= o2) sc += nb;
        }
        if (lane == 31) eqs[w] = sc;            // eqs region as warp-sum scratch
        __syncthreads();
        if (tid == 0) {
            float a = 0.0f;
#pragma unroll
            for (int i2 = 0; i2 < 8; i2++) { a += eqs[i2]; eks[i2] = a; }
        }
        __syncthreads();
        float run = (w > 0 ? eks[w - 1] : 0.0f) + (sc - ts);
#pragma unroll
        for (int j = 0; j < 4; j++) {
            run += gv[j];
            int ix = bse + j;
            if (ix < nsc) scr[ix] = run;
        }
        __syncthreads();
        if (tid < BT) eqs[tid] = expf(scr[row0 - lo + tid]);
    }

    float o[16] = {};                       // O accum: 4 n8-tiles x 4
    int r0 = m0 + (lane >> 2);
    int cq = (lane & 3) * 2;

    // lane-constant address pieces
    unsigned a_row = (unsigned)(m0 + (lane & 15)) * SLD;   // A frag rows
    unsigned a_k8  = ((lane >> 4) << 3);                   // A k-half per 16 lanes
    unsigned b_row = (unsigned)(((lane >> 4) << 3) + (lane & 7));  // GEMM1 B: n rows
    unsigned b_k8  = (((lane >> 3) & 1) << 3);                     // GEMM1 B: k-half
    unsigned v_row = (unsigned)((lane & 7) + (((lane >> 3) & 1) << 3)); // GEMM2 V: k row
    unsigned v_col = ((lane >> 4) << 3);                                // GEMM2 V: n-half

    // prefetch first K/V tile into registers
    float4 kf[4], vf[4];
    {
        const float* ks = k + ((size_t)(b * T_ + ct0 * BT) * H_ + h) * D_;
        const float* vs = v + ((size_t)(b * T_ + ct0 * BT) * H_ + h) * D_;
#pragma unroll
        for (int it = 0; it < 4; it++) {
            kf[it] = *(const float4*)(ks + (size_t)pr[it] * (H_ * D_) + pc[it]);
            vf[it] = *(const float4*)(vs + (size_t)pr[it] * (H_ * D_) + pc[it]);
        }
    }

    for (int ct = ct0; ct <= ct1; ct++) {
        __syncthreads();                    // prev GEMM2 finished reading smem
#pragma unroll
        for (int it = 0; it < 4; it++) {
            unsigned off = (unsigned)(pr[it] * SLD + pc[it]) * 2;
            split_store(kf[it], sm + O_KH, sm + O_KL, off);
            split_store(vf[it], sm + O_VH, sm + O_VL, off);
        }
        if (tid < BT) eks[tid] = expf(-scr[ct * BT - lo + tid]);
        __syncthreads();

        // ---- GEMM1: S = Qh*Kh + Qh*Kl + Ql*Kh (hoisted fragments) ----
        float sa[16] = {};
#pragma unroll
        for (int kk = 0; kk < 4; kk++) {
            unsigned k0 = kk * 16;
            unsigned ah0, ah1, ah2, ah3, al0, al1, al2, al3;
            LDSM4(ah0, ah1, ah2, ah3, su + O_QH + (a_row + k0 + a_k8) * 2);
            LDSM4(al0, al1, al2, al3, su + O_QL + (a_row + k0 + a_k8) * 2);
#pragma unroll
            for (int nn = 0; nn < 2; nn++) {
                unsigned off = (((unsigned)(n0 + nn * 16) + b_row) * SLD + k0 + b_k8) * 2;
                unsigned bh0, bh1, bh2, bh3, bl0, bl1, bl2, bl3;
                LDSM4(bh0, bh1, bh2, bh3, su + O_KH + off);
                LDSM4(bl0, bl1, bl2, bl3, su + O_KL + off);
                float* s0 = sa + nn * 8;
                float* s1 = sa + nn * 8 + 4;
                MMA16816(s0, ah0, ah1, ah2, ah3, bh0, bh1);
                MMA16816(s1, ah0, ah1, ah2, ah3, bh2, bh3);
                MMA16816(s0, ah0, ah1, ah2, ah3, bl0, bl1);
                MMA16816(s1, ah0, ah1, ah2, ah3, bl2, bl3);
                MMA16816(s0, al0, al1, al2, al3, bh0, bh1);
                MMA16816(s1, al0, al1, al2, al3, bh2, bh3);
            }
        }

        // ---- epilogue: hierarchical weight, split, store to S tiles ----
        bool diag = (ct == rt);
        float eq0 = eqs[r0], eq1 = eqs[r0 + 8];
        float rw0 = 0.f, rw1 = 0.f;
        if (!diag) {
            int lev = 6 + (32 - __clz(rt ^ ct));
            rw0 = eq0 * Lss[lev * 64 + r0];
            rw1 = eq1 * Lss[lev * 64 + r0 + 8];
        }
#pragma unroll
        for (int j = 0; j < 4; j++) {
            // sa layout: j = nn*2 + t8 where t8 = n8-tile within nn
            int c0 = n0 + j * 8 + cq;
            float ek0 = eks[c0], ek1 = eks[c0 + 1];
            float s00 = sa[j * 4 + 0], s01 = sa[j * 4 + 1];
            float s10 = sa[j * 4 + 2], s11 = sa[j * 4 + 3];
            if (!diag) {
                s00 *= rw0 * ek0; s01 *= rw0 * ek1;
                s10 *= rw1 * ek0; s11 *= rw1 * ek1;
            } else {
                int x;
                x = r0 ^ c0;
                s00 = (c0 > r0) ? 0.f : s00 * eq0 * ek0 * Lss[(x ? 32 - __clz(x) : 0) * 64 + r0];
                x = r0 ^ (c0 + 1);
                s01 = (c0 + 1 > r0) ? 0.f : s01 * eq0 * ek1 * Lss[(x ? 32 - __clz(x) : 0) * 64 + r0];
                x = (r0 + 8) ^ c0;
                s10 = (c0 > r0 + 8) ? 0.f : s10 * eq1 * ek0 * Lss[(x ? 32 - __clz(x) : 0) * 64 + r0 + 8];
                x = (r0 + 8) ^ (c0 + 1);
                s11 = (c0 + 1 > r0 + 8) ? 0.f : s11 * eq1 * ek1 * Lss[(x ? 32 - __clz(x) : 0) * 64 + r0 + 8];
            }
            unsigned h0 = ((__float_as_uint(s00) & 0xFFFF0000u) >> 16) | (__float_as_uint(s01) & 0xFFFF0000u);
            unsigned h1 = ((__float_as_uint(s10) & 0xFFFF0000u) >> 16) | (__float_as_uint(s11) & 0xFFFF0000u);
            float t00 = s00 - __uint_as_float(__float_as_uint(s00) & 0xFFFF0000u);
            float t01 = s01 - __uint_as_float(__float_as_uint(s01) & 0xFFFF0000u);
            float t10 = s10 - __uint_as_float(__float_as_uint(s10) & 0xFFFF0000u);
            float t11 = s11 - __uint_as_float(__float_as_uint(s11) & 0xFFFF0000u);
            unsigned off0 = (unsigned)(r0 * SLD + c0) * 2;
            unsigned off1 = (unsigned)((r0 + 8) * SLD + c0) * 2;
            *(unsigned*)(sm + O_SH + off0) = h0;
            *(unsigned*)(sm + O_SH + off1) = h1;
            *(unsigned*)(sm + O_SL + off0) = pack_lo2(t00, t01);
            *(unsigned*)(sm + O_SL + off1) = pack_lo2(t10, t11);
        }

        // prefetch next tile's K/V (overlaps with GEMM2 below)
        if (ct < ct1) {
            const float* ks = k + ((size_t)(b * T_ + (ct + 1) * BT) * H_ + h) * D_;
            const float* vs = v + ((size_t)(b * T_ + (ct + 1) * BT) * H_ + h) * D_;
#pragma unroll
            for (int it = 0; it < 4; it++) {
                kf[it] = *(const float4*)(ks + (size_t)pr[it] * (H_ * D_) + pc[it]);
                vf[it] = *(const float4*)(vs + (size_t)pr[it] * (H_ * D_) + pc[it]);
            }
        }
        __syncthreads();

        // ---- GEMM2: O += Sh*Vh + Sh*Vl + Sl*Vh (hoisted fragments) ----
#pragma unroll
        for (int kk = 0; kk < 4; kk++) {
            unsigned k0 = kk * 16;
            unsigned ah0, ah1, ah2, ah3, al0, al1, al2, al3;
            LDSM4(ah0, ah1, ah2, ah3, su + O_SH + (a_row + k0 + a_k8) * 2);
            LDSM4(al0, al1, al2, al3, su + O_SL + (a_row + k0 + a_k8) * 2);
#pragma unroll
            for (int nn = 0; nn < 2; nn++) {
                unsigned va = ((k0 + v_row) * SLD + (unsigned)(n0 + nn * 16) + v_col) * 2;
                unsigned bh0, bh1, bh2, bh3, bl0, bl1, bl2, bl3;
                LDSM4T(bh0, bh1, bh2, bh3, su + O_VH + va);
                LDSM4T(bl0, bl1, bl2, bl3, su + O_VL + va);
                float* o0 = o + nn * 8;
                float* o1 = o + nn * 8 + 4;
                MMA16816(o0, ah0, ah1, ah2, ah3, bh0, bh1);
                MMA16816(o1, ah0, ah1, ah2, ah3, bh2, bh3);
                MMA16816(o0, ah0, ah1, ah2, ah3, bl0, bl1);
                MMA16816(o1, ah0, ah1, ah2, ah3, bl2, bl3);
                MMA16816(o0, al0, al1, al2, al3, bh0, bh1);
                MMA16816(o1, al0, al1, al2, al3, bh2, bh3);
            }
        }
    }

    // ---- output: direct write (nch==1) or split-K partial + fused reduce ----
    if (nch == 1) {
        float* ob = out + ((size_t)(b * T_ + row0) * H_ + h) * D_;
#pragma unroll
        for (int j = 0; j < 4; j++) {
            int c0 = n0 + j * 8 + cq;
            *(float2*)(ob + (size_t)r0 * (H_ * D_) + c0)       = make_float2(o[j * 4 + 0], o[j * 4 + 1]);
            *(float2*)(ob + (size_t)(r0 + 8) * (H_ * D_) + c0) = make_float2(o[j * 4 + 2], o[j * 4 + 3]);
        }
    } else {
        float* pb = g_part + ((size_t)((bh * NRT + rt) * 4 + ci)) * BT * D_;
#pragma unroll
        for (int j = 0; j < 4; j++) {
            int c0 = n0 + j * 8 + cq;
            *(float2*)(pb + r0 * D_ + c0)       = make_float2(o[j * 4 + 0], o[j * 4 + 1]);
            *(float2*)(pb + (r0 + 8) * D_ + c0) = make_float2(o[j * 4 + 2], o[j * 4 + 3]);
        }
        __threadfence();
        __syncthreads();
        if (tid == 0)
            lastFlag = (atomicAdd(&g_cnt[bh * NRT + rt], 1) == nch - 1);
        __syncthreads();
        if (lastFlag) {
            const float* p0 = g_part + ((size_t)((bh * NRT + rt) * 4)) * BT * D_;
            float* ob = out + ((size_t)(b * T_ + row0) * H_ + h) * D_;
            for (int i2 = tid; i2 < BT * D_ / 4; i2 += NTHREADS) {
                int li = i2 >> 4, p4 = (i2 & 15) * 4;
                float4 s = __ldcg((const float4*)(p0 + (size_t)i2 * 4));
                for (int c = 1; c < nch; c++) {
                    float4 t = __ldcg((const float4*)(p0 + (size_t)c * BT * D_ + (size_t)i2 * 4));
                    s.x += t.x; s.y += t.y; s.z += t.z; s.w += t.w;
                }
                *(float4*)(ob + (size_t)li * (H_ * D_) + p4) = s;
            }
            __syncthreads();
            if (tid == 0) g_cnt[bh * NRT + rt] = 0;   // reset for next replay
        }
    }
}

extern "C" void kernel_launch(void* const* d_in, const int* in_sizes, int n_in,
                              void* d_out, int out_size) {
    const float* q   = (const float*)d_in[0];
    const float* k   = (const float*)d_in[1];
    const float* v   = (const float*)d_in[2];
    const float* g   = (const float*)d_in[3];
    const float* Lsc = (const float*)d_in[4];
    float* out = (float*)d_out;

    cudaFuncSetAttribute(hattn_kernel, cudaFuncAttributeMaxDynamicSharedMemorySize, SMEM_TOTAL);
    hattn_kernel<<<NBH * UPB, NTHREADS, SMEM_TOTAL>>>(q, k, v, g, Lsc, out);
}

// round 17
// speedup vs baseline: 3.6978x; 1.1232x over previous
#include <cuda_runtime.h>

#define B_ 2
#define T_ 1024
#define H_ 8
#define D_ 64
#define NLEV_ 11
#define RT_ROWS 128          // row tile
#define CT_COLS 64           // col tile
#define SLD 72               // elems per smem row (64+8 pad) -> 144B
#define NTHREADS 256
#define NBH (B_*H_)
#define NRT8 (T_/RT_ROWS)    // 8 row tiles
#define CHUNK 4
#define UPB 20               // per-bh units: sum over rt8 of (rt8>>1)+1

// smem byte offsets
#define O_QH 0
#define O_QL 18432
#define O_KH 36864
#define O_KL 46080
#define O_VH 55296
#define O_VL 64512
#define O_LS 73728           // 11*128 floats = 5632
#define O_EQ 79360           // 128 floats
#define O_EK 79872           // 64 floats
#define O_SCR 80128          // 1024 floats
#define SMEM_TOTAL 84224

__device__ float g_part[NBH * NRT8 * 4 * RT_ROWS * CT_COLS];  // 16.8 MB
__device__ int   g_cnt[NBH * NRT8];                           // zero-init

__device__ __forceinline__ unsigned su32(const void* p) {
    unsigned a;
    asm("{ .reg .u64 t; cvta.to.shared.u64 t, %1; cvt.u32.u64 %0, t; }" : "=r"(a) : "l"(p));
    return a;
}
#define LDSM4(r0,r1,r2,r3,a) \
    asm volatile("ldmatrix.sync.aligned.m8n8.x4.shared.b16 {%0,%1,%2,%3}, [%4];" \
                 : "=r"(r0),"=r"(r1),"=r"(r2),"=r"(r3) : "r"(a))
#define LDSM4T(r0,r1,r2,r3,a) \
    asm volatile("ldmatrix.sync.aligned.m8n8.x4.trans.shared.b16 {%0,%1,%2,%3}, [%4];" \
                 : "=r"(r0),"=r"(r1),"=r"(r2),"=r"(r3) : "r"(a))
#define MMA16816(d,a0,a1,a2,a3,b0,b1) \
    asm volatile("mma.sync.aligned.m16n8k16.row.col.f32.bf16.bf16.f32 " \
                 "{%0,%1,%2,%3},{%4,%5,%6,%7},{%8,%9},{%0,%1,%2,%3};" \
                 : "+f"((d)[0]),"+f"((d)[1]),"+f"((d)[2]),"+f"((d)[3]) \
                 : "r"(a0),"r"(a1),"r"(a2),"r"(a3),"r"(b0),"r"(b1))

__device__ __forceinline__ unsigned pack_lo2(float x, float y) {
    unsigned r;
    asm("cvt.rn.bf16x2.f32 %0, %1, %2;" : "=r"(r) : "f"(y), "f"(x));  // x->low
    return r;
}
__device__ __forceinline__ void split_store(float4 f, char* hi, char* lo, unsigned off) {
    unsigned bx = __float_as_uint(f.x) & 0xFFFF0000u;
    unsigned by = __float_as_uint(f.y) & 0xFFFF0000u;
    unsigned bz = __float_as_uint(f.z) & 0xFFFF0000u;
    unsigned bw = __float_as_uint(f.w) & 0xFFFF0000u;
    unsigned h01 = (bx >> 16) | by, h23 = (bz >> 16) | bw;
    unsigned l01 = pack_lo2(f.x - __uint_as_float(bx), f.y - __uint_as_float(by));
    unsigned l23 = pack_lo2(f.z - __uint_as_float(bz), f.w - __uint_as_float(bw));
    *(uint2*)(hi + off) = make_uint2(h01, h23);
    *(uint2*)(lo + off) = make_uint2(l01, l23);
}

// ---------------------------------------------------------------------------
__global__ __launch_bounds__(NTHREADS, 2) void hattn_kernel(
    const float* __restrict__ q, const float* __restrict__ k,
    const float* __restrict__ v, const float* __restrict__ gates,
    const float* __restrict__ Lsc, float* __restrict__ out)
{
    extern __shared__ char sm[];
    __shared__ int lastFlag;
    unsigned su = su32(sm);
    float* eqs = (float*)(sm + O_EQ);
    float* eks = (float*)(sm + O_EK);
    float* Lss = (float*)(sm + O_LS);
    float* scr = (float*)(sm + O_SCR);

    int bh = blockIdx.x & (NBH - 1);
    int u  = blockIdx.x >> 4;
    int rt8 = NRT8 - 1;
    while (u >= ((rt8 >> 1) + 1)) { u -= (rt8 >> 1) + 1; rt8--; }
    int ci = u;
    int nct = 2 * rt8 + 2;
    int ct0 = ci * CHUNK;
    int ct1 = ct0 + CHUNK - 1; if (ct1 > nct - 1) ct1 = nct - 1;
    int nch = (rt8 >> 1) + 1;

    int b = bh >> 3, h = bh & 7;
    int tid = threadIdx.x, lane = tid & 31, w = tid >> 5;
    int m0 = w * 16;
    int rb = 2 * rt8 + (w >> 2);           // this warp's 64-row block index
    int row0 = rt8 * RT_ROWS;
    int lo = ct0 * CT_COLS;
    int nsc = row0 + RT_ROWS - lo;         // scan span (<=1024)

    // ---- load + split Q tile [128 x 64] ----
    {
        const float* qs = q + ((size_t)(b * T_ + row0) * H_ + h) * D_;
#pragma unroll
        for (int it = 0; it < 8; it++) {
            int idx = tid + it * NTHREADS;
            int r = idx >> 4, c4 = (idx & 15) << 2;
            float4 f = *(const float4*)(qs + (size_t)r * (H_ * D_) + c4);
            split_store(f, sm + O_QH, sm + O_QL, (unsigned)(r * SLD + c4) * 2);
        }
    }
    for (int idx = tid; idx < NLEV_ * RT_ROWS; idx += NTHREADS) {
        int lev = idx >> 7, l = idx & 127;
        Lss[idx] = Lsc[((size_t)(bh * NLEV_ + lev)) * T_ + row0 + l];
    }

    // ---- CTA-local inclusive scan of gates over [lo, row0+128) ----
    {
        float gv[4];
        int bse = tid * 4;
        const float* gp = gates + ((size_t)(b * T_ + lo)) * H_ + h;
#pragma unroll
        for (int j = 0; j < 4; j++) {
            int ix = bse + j;
            gv[j] = (ix < nsc) ? gp[(size_t)ix * H_] : 0.0f;
        }
        float ts = gv[0] + gv[1] + gv[2] + gv[3];
        float sc = ts;
#pragma unroll
        for (int o2 = 1; o2 < 32; o2 <<= 1) {
            float nb = __shfl_up_sync(0xFFFFFFFFu, sc, o2);
            if (lane >= o2) sc += nb;
        }
        if (lane == 31) eqs[w] = sc;
        __syncthreads();
        if (tid == 0) {
            float a = 0.0f;
#pragma unroll
            for (int i2 = 0; i2 < 8; i2++) { a += eqs[i2]; eks[i2] = a; }
        }
        __syncthreads();
        float run = (w > 0 ? eks[w - 1] : 0.0f) + (sc - ts);
#pragma unroll
        for (int j = 0; j < 4; j++) {
            run += gv[j];
            int ix = bse + j;
            if (ix < nsc) scr[ix] = run;
        }
        __syncthreads();
        if (tid < RT_ROWS) eqs[tid] = expf(scr[row0 - lo + tid]);
        __syncthreads();   // eqs visible to ALL warps before cross-warp reads
    }

    float o[32] = {};                       // O accum: 8 n8-tiles x 4 (16x64)
    int r0 = m0 + (lane >> 2);
    int cq = (lane & 3) * 2;

    // lane-constant address pieces (same verified mappings)
    unsigned a_row = (unsigned)(m0 + (lane & 15)) * SLD;
    unsigned a_k8  = ((lane >> 4) << 3);
    unsigned b_row = (unsigned)(((lane >> 4) << 3) + (lane & 7));
    unsigned b_k8  = (((lane >> 3) & 1) << 3);
    unsigned v_row = (unsigned)((lane & 7) + (((lane >> 3) & 1) << 3));
    unsigned v_col = ((lane >> 4) << 3);

    float eq0 = eqs[r0], eq1 = eqs[r0 + 8];

    for (int ct = ct0; ct <= ct1; ct++) {
        __syncthreads();                    // prev GEMM2 done reading K/V smem
        {
            const float* ks = k + ((size_t)(b * T_ + ct * CT_COLS) * H_ + h) * D_;
            const float* vs = v + ((size_t)(b * T_ + ct * CT_COLS) * H_ + h) * D_;
#pragma unroll
            for (int it = 0; it < 4; it++) {
                int idx = tid + it * NTHREADS;
                int r = idx >> 4, c4 = (idx & 15) << 2;
                unsigned off = (unsigned)(r * SLD + c4) * 2;
                split_store(*(const float4*)(ks + (size_t)r * (H_ * D_) + c4),
                            sm + O_KH, sm + O_KL, off);
                split_store(*(const float4*)(vs + (size_t)r * (H_ * D_) + c4),
                            sm + O_VH, sm + O_VL, off);
            }
        }
        if (tid < CT_COLS) eks[tid] = expf(-scr[ct * CT_COLS - lo + tid]);
        __syncthreads();

        if (ct > rb) continue;              // warp strip entirely above diagonal

        // ---- GEMM1: S(16x64) = Qh*Kh + Qh*Kl + Ql*Kh ----
        float sa[32] = {};
#pragma unroll
        for (int kk = 0; kk < 4; kk++) {
            unsigned k0 = kk * 16;
            unsigned ah0, ah1, ah2, ah3, al0, al1, al2, al3;
            LDSM4(ah0, ah1, ah2, ah3, su + O_QH + (a_row + k0 + a_k8) * 2);
            LDSM4(al0, al1, al2, al3, su + O_QL + (a_row + k0 + a_k8) * 2);
#pragma unroll
            for (int nn = 0; nn < 4; nn++) {
                unsigned off = (((unsigned)(nn * 16) + b_row) * SLD + k0 + b_k8) * 2;
                unsigned bh0, bh1, bh2, bh3, bl0, bl1, bl2, bl3;
                LDSM4(bh0, bh1, bh2, bh3, su + O_KH + off);
                LDSM4(bl0, bl1, bl2, bl3, su + O_KL + off);
                float* s0 = sa + nn * 8;
                float* s1 = sa + nn * 8 + 4;
                MMA16816(s0, ah0, ah1, ah2, ah3, bh0, bh1);
                MMA16816(s1, ah0, ah1, ah2, ah3, bh2, bh3);
                MMA16816(s0, ah0, ah1, ah2, ah3, bl0, bl1);
                MMA16816(s1, ah0, ah1, ah2, ah3, bl2, bl3);
                MMA16816(s0, al0, al1, al2, al3, bh0, bh1);
                MMA16816(s1, al0, al1, al2, al3, bh2, bh3);
            }
        }

        // ---- epilogue in registers: weight + split to A-fragments ----
        bool diag = (ct == rb);
        float rw0 = 0.f, rw1 = 0.f;
        if (!diag) {
            int lev = 6 + (32 - __clz(rb ^ ct));
            rw0 = eq0 * Lss[lev * 128 + r0];
            rw1 = eq1 * Lss[lev * 128 + r0 + 8];
        }
        unsigned shi[16], slo[16];
        int lrm0 = r0 & 63, lrm1 = (r0 + 8) & 63;
#pragma unroll
        for (int j = 0; j < 8; j++) {
            int c0 = j * 8 + cq;
            float ek0 = eks[c0], ek1 = eks[c0 + 1];
            float s00 = sa[j * 4 + 0], s01 = sa[j * 4 + 1];
            float s10 = sa[j * 4 + 2], s11 = sa[j * 4 + 3];
            if (!diag) {
                s00 *= rw0 * ek0; s01 *= rw0 * ek1;
                s10 *= rw1 * ek0; s11 *= rw1 * ek1;
            } else {
                int x;
                x = lrm0 ^ c0;
                s00 = (c0 > lrm0) ? 0.f : s00 * eq0 * ek0 * Lss[(x ? 32 - __clz(x) : 0) * 128 + r0];
                x = lrm0 ^ (c0 + 1);
                s01 = (c0 + 1 > lrm0) ? 0.f : s01 * eq0 * ek1 * Lss[(x ? 32 - __clz(x) : 0) * 128 + r0];
                x = lrm1 ^ c0;
                s10 = (c0 > lrm1) ? 0.f : s10 * eq1 * ek0 * Lss[(x ? 32 - __clz(x) : 0) * 128 + r0 + 8];
                x = lrm1 ^ (c0 + 1);
                s11 = (c0 + 1 > lrm1) ? 0.f : s11 * eq1 * ek1 * Lss[(x ? 32 - __clz(x) : 0) * 128 + r0 + 8];
            }
            unsigned u0 = __float_as_uint(s00), u1 = __float_as_uint(s01);
            unsigned u2 = __float_as_uint(s10), u3 = __float_as_uint(s11);
            int sb = (j >> 1) * 4 + (j & 1) * 2;
            shi[sb]     = ((u0 & 0xFFFF0000u) >> 16) | (u1 & 0xFFFF0000u);
            shi[sb + 1] = ((u2 & 0xFFFF0000u) >> 16) | (u3 & 0xFFFF0000u);
            slo[sb]     = pack_lo2(s00 - __uint_as_float(u0 & 0xFFFF0000u),
                                   s01 - __uint_as_float(u1 & 0xFFFF0000u));
            slo[sb + 1] = pack_lo2(s10 - __uint_as_float(u2 & 0xFFFF0000u),
                                   s11 - __uint_as_float(u3 & 0xFFFF0000u));
        }

        // ---- GEMM2: O += Sh*Vh + Sh*Vl + Sl*Vh  (S from registers) ----
#pragma unroll
        for (int kk = 0; kk < 4; kk++) {
            unsigned k0 = kk * 16;
            unsigned ah0 = shi[kk * 4], ah1 = shi[kk * 4 + 1], ah2 = shi[kk * 4 + 2], ah3 = shi[kk * 4 + 3];
            unsigned al0 = slo[kk * 4], al1 = slo[kk * 4 + 1], al2 = slo[kk * 4 + 2], al3 = slo[kk * 4 + 3];
#pragma unroll
            for (int nn = 0; nn < 4; nn++) {
                unsigned va = ((k0 + v_row) * SLD + (unsigned)(nn * 16) + v_col) * 2;
                unsigned bh0, bh1, bh2, bh3, bl0, bl1, bl2, bl3;
                LDSM4T(bh0, bh1, bh2, bh3, su + O_VH + va);
                LDSM4T(bl0, bl1, bl2, bl3, su + O_VL + va);
                float* o0 = o + nn * 8;
                float* o1 = o + nn * 8 + 4;
                MMA16816(o0, ah0, ah1, ah2, ah3, bh0, bh1);
                MMA16816(o1, ah0, ah1, ah2, ah3, bh2, bh3);
                MMA16816(o0, ah0, ah1, ah2, ah3, bl0, bl1);
                MMA16816(o1, ah0, ah1, ah2, ah3, bl2, bl3);
                MMA16816(o0, al0, al1, al2, al3, bh0, bh1);
                MMA16816(o1, al0, al1, al2, al3, bh2, bh3);
            }
        }
    }

    // ---- output: direct (nch==1) or split-K partial + fused reduce ----
    if (nch == 1) {
        float* ob = out + ((size_t)(b * T_ + row0) * H_ + h) * D_;
#pragma unroll
        for (int j = 0; j < 8; j++) {
            int c0 = j * 8 + cq;
            *(float2*)(ob + (size_t)r0 * (H_ * D_) + c0)       = make_float2(o[j * 4 + 0], o[j * 4 + 1]);
            *(float2*)(ob + (size_t)(r0 + 8) * (H_ * D_) + c0) = make_float2(o[j * 4 + 2], o[j * 4 + 3]);
        }
    } else {
        float* pb = g_part + ((size_t)((bh * NRT8 + rt8) * 4 + ci)) * RT_ROWS * CT_COLS;
#pragma unroll
        for (int j = 0; j < 8; j++) {
            int c0 = j * 8 + cq;
            *(float2*)(pb + r0 * CT_COLS + c0)       = make_float2(o[j * 4 + 0], o[j * 4 + 1]);
            *(float2*)(pb + (r0 + 8) * CT_COLS + c0) = make_float2(o[j * 4 + 2], o[j * 4 + 3]);
        }
        __threadfence();
        __syncthreads();
        if (tid == 0)
            lastFlag = (atomicAdd(&g_cnt[bh * NRT8 + rt8], 1) == nch - 1);
        __syncthreads();
        if (lastFlag) {
            const float* p0 = g_part + ((size_t)((bh * NRT8 + rt8) * 4)) * RT_ROWS * CT_COLS;
            float* ob = out + ((size_t)(b * T_ + row0) * H_ + h) * D_;
            for (int i2 = tid; i2 < RT_ROWS * CT_COLS / 4; i2 += NTHREADS) {
                int li = i2 >> 4, p4 = (i2 & 15) * 4;
                float4 s = __ldcg((const float4*)(p0 + (size_t)i2 * 4));
                for (int c = 1; c < nch; c++) {
                    float4 t = __ldcg((const float4*)(p0 + (size_t)c * RT_ROWS * CT_COLS + (size_t)i2 * 4));
                    s.x += t.x; s.y += t.y; s.z += t.z; s.w += t.w;
                }
                *(float4*)(ob + (size_t)li * (H_ * D_) + p4) = s;
            }
            __syncthreads();
            if (tid == 0) g_cnt[bh * NRT8 + rt8] = 0;   // reset for next replay
        }
    }
}

extern "C" void kernel_launch(void* const* d_in, const int* in_sizes, int n_in,
                              void* d_out, int out_size) {
    const float* q   = (const float*)d_in[0];
    const float* k   = (const float*)d_in[1];
    const float* v   = (const float*)d_in[2];
    const float* g   = (const float*)d_in[3];
    const float* Lsc = (const float*)d_in[4];
    float* out = (float*)d_out;

    cudaFuncSetAttribute(hattn_kernel, cudaFuncAttributeMaxDynamicSharedMemorySize, SMEM_TOTAL);
    hattn_kernel<<<NBH * UPB, NTHREADS, SMEM_TOTAL>>>(q, k, v, g, Lsc, out);
}